// round 15
// baseline (speedup 1.0000x reference)
#include <cuda_runtime.h>
#include <math.h>

#define DD     32
#define DIMN   16
#define NTOT   4096
#define EPSV   1e-5f
#define LAM    0.1f
#define NSWEEP 4
#define WPB    2       // warps per block; each warp solves 2 matrices (lane halves)

// ---------------- scratch (device globals: no allocation allowed) -----------
struct ZeroBlock {
    float2 G[DIMN * DIMN];   // sum_d A_d A_d^H (atomic accumulate)
    double acc;              // loss accumulator
    unsigned int cnt;        // completion ticket
};
__device__ ZeroBlock g_Z;
__device__ float2 g_S[DD * DIMN * DIMN];       // A_d + A_d^H
__device__ float2 g_r[DD * DIMN];              // column sums of A_d
__device__ float2 g_r2[DD * DIMN];             // column sums of A_d @ A_d

__device__ __forceinline__ float frcp(float a) {
    float r; asm("rcp.approx.f32 %0,%1;" : "=f"(r) : "f"(a)); return r;
}
__device__ __forceinline__ float fsqrt_ap(float a) {
    float r; asm("sqrt.approx.f32 %0,%1;" : "=f"(r) : "f"(a)); return r;
}

// ---------------- kernel 0: constants from A (one block per d, atomic G) ----
__global__ void precompute_kernel(const float* __restrict__ Ar,
                                  const float* __restrict__ Ai) {
    __shared__ float2 sr[DIMN];
    const int d = blockIdx.x;
    const int t = threadIdx.x;          // 256 threads, one per (i,j)
    const int i = t >> 4, j = t & 15;
    const float* ar = Ar + d * 256;
    const float* ai = Ai + d * 256;

    float arij = ar[i * 16 + j], aiij = ai[i * 16 + j];
    float arji = ar[j * 16 + i], aiji = ai[j * 16 + i];
    g_S[d * 256 + t] = make_float2(arij + arji, aiij - aiji);

    float gx = 0.f, gy = 0.f;
    #pragma unroll
    for (int k = 0; k < 16; k++) {
        float axr = ar[i * 16 + k], axi = ai[i * 16 + k];
        float bxr = ar[j * 16 + k], bxi = ai[j * 16 + k];
        gx += axr * bxr + axi * bxi;
        gy += axi * bxr - axr * bxi;
    }
    atomicAdd(&g_Z.G[t].x, gx);
    atomicAdd(&g_Z.G[t].y, gy);

    if (t < 16) {
        float2 s = make_float2(0.f, 0.f);
        #pragma unroll
        for (int ii = 0; ii < 16; ii++) {
            s.x += ar[ii * 16 + t];
            s.y += ai[ii * 16 + t];
        }
        sr[t] = s;
        g_r[d * 16 + t] = s;
    }
    __syncthreads();
    if (t < 16) {
        float2 s = make_float2(0.f, 0.f);
        #pragma unroll
        for (int k = 0; k < 16; k++) {
            float2 rk = sr[k];
            float axr = ar[k * 16 + t], axi = ai[k * 16 + t];
            s.x += rk.x * axr - rk.y * axi;
            s.y += rk.x * axi + rk.y * axr;
        }
        g_r2[d * 16 + t] = s;
    }
}

// ---------------- kernel 1: split-warp Jacobi, 2 matrices per warp ----------
// Matrix (lane>>4) lives in that 16-lane half: 8 column-pairs x 2 lanes,
// each lane holds rows {2r + (hl&1)} of columns {2*g2, 2*g2+1}.
__global__ void __launch_bounds__(WPB * 32)
solve_kernel(const float* __restrict__ X, float* __restrict__ out) {
    __shared__ float2 sH[WPB][DIMN * 17];        // build/transpose buffer
    __shared__ float2 spsi[WPB][2][DIMN];

    const int w     = threadIdx.x >> 5;
    const int lane  = threadIdx.x & 31;
    const int nbase = (blockIdx.x * WPB + w) * 2;
    const unsigned FULL = 0xffffffffu;

    const int m   = lane >> 4;       // which matrix of the pair
    const int hl  = lane & 15;       // lane within half
    const int g2  = hl >> 1;         // column-pair group 0..7
    const int rl2 = hl & 1;          // row parity within group

    float2* H = sH[w];
    float2 T[8], B[8];
    float  x2[2];
    float  nrmT, nrmB;

    // ---- build both H matrices (full warp per matrix, buffer reused) ----
    x2[0] = X[nbase * DD + lane];
    x2[1] = X[(nbase + 1) * DD + lane];

    #pragma unroll
    for (int mm = 0; mm < 2; mm++) {
        float sx2 = x2[mm] * x2[mm];
        #pragma unroll
        for (int o = 16; o > 0; o >>= 1) sx2 += __shfl_xor_sync(FULL, sx2, o);

        float2 acc[8];
        #pragma unroll
        for (int k = 0; k < 8; k++) {
            float2 gg = g_Z.G[k * 32 + lane];
            acc[k] = make_float2(0.5f * gg.x, 0.5f * gg.y);
        }
        #pragma unroll
        for (int d = 0; d < DD; d++) {
            float h = 0.5f * __shfl_sync(FULL, x2[mm], d);
            #pragma unroll
            for (int k = 0; k < 8; k++) {
                float2 s = g_S[d * 256 + k * 32 + lane];
                acc[k].x -= h * s.x;
                acc[k].y -= h * s.y;
            }
        }
        #pragma unroll
        for (int k = 0; k < 8; k++) {
            int e = k * 32 + lane;
            int i = e >> 4, j = e & 15;
            if (i == j) acc[k].x += EPSV + 0.5f * sx2;
            H[i * 17 + j] = acc[k];
        }
        __syncwarp();
        if (m == mm) {
            #pragma unroll
            for (int r = 0; r < 8; r++) {
                T[r] = H[(2 * r + rl2) * 17 + 2 * g2];
                B[r] = H[(2 * r + rl2) * 17 + 2 * g2 + 1];
            }
        }
        __syncwarp();
    }

    // exact initial column norms + prologue Gram for round 0
    float bx, by;
    {
        float a = 0.f, d0 = 0.f, gx = 0.f, gy = 0.f;
        #pragma unroll
        for (int r = 0; r < 8; r++) {
            a  += T[r].x * T[r].x + T[r].y * T[r].y;
            d0 += B[r].x * B[r].x + B[r].y * B[r].y;
            gx += T[r].x * B[r].x + T[r].y * B[r].y;
            gy += T[r].x * B[r].y - T[r].y * B[r].x;
        }
        a  += __shfl_xor_sync(FULL, a,  1);
        d0 += __shfl_xor_sync(FULL, d0, 1);
        gx += __shfl_xor_sync(FULL, gx, 1);
        gy += __shfl_xor_sync(FULL, gy, 1);
        nrmT = a; nrmB = d0; bx = gx; by = gy;
    }

    // ---- one-sided Jacobi, round-robin, tracked norms, pipelined Gram ----
    // Closed-form rotation: rho = sqrt(df^2+4|b|^2); c^2=(rho+|df|)/(2rho);
    // (s/|b|)^2 = 2/(rho(rho+|df|)); delta = 2|b|^2/(rho+|df|)
    const int NROUND = NSWEEP * 15;
    for (int it = 0; it < NROUND - 1; it++) {
        // rotation params from the Gram accumulated at the previous bottom
        float df   = nrmB - nrmT;
        float ab2  = fmaxf(bx * bx + by * by, 1e-30f);
        float rho2 = fmaf(df, df, 4.f * ab2);
        float rrho = rsqrtf(rho2);
        float rho  = rho2 * rrho;
        float adf  = fabsf(df);
        float rpa  = rho + adf;
        float rca  = frcp(rpa);
        float sgn  = (df >= 0.f) ? 1.f : -1.f;
        float hrr  = 0.5f * rrho;
        float c    = fsqrt_ap(rpa * hrr);
        float inv  = sgn * fsqrt_ap(4.f * hrr * rca);   // s/|b|
        float delta = sgn * (2.f * ab2) * rca;
        float wx = bx * inv, wy = by * inv;
        float a2 = nrmT - delta;
        float d2 = nrmB + delta;

        // column update + fused permutation + NEXT-round Gram accumulation
        float gx = 0.f, gy = 0.f;
        #pragma unroll
        for (int r = 0; r < 8; r++) {
            float tx = T[r].x, ty = T[r].y;
            float bxr = B[r].x, byr = B[r].y;
            float ntx = c * tx - (wx * bxr + wy * byr);
            float nty = c * ty - (wx * byr - wy * bxr);
            float nbx = (wx * tx - wy * ty) + c * bxr;
            float nby = (wx * ty + wy * tx) + c * byr;

            float selx = (g2 == 0) ? nbx : ntx;
            float sely = (g2 == 0) ? nby : nty;
            float upx = __shfl_sync(FULL, selx, lane - 2);
            float upy = __shfl_sync(FULL, sely, lane - 2);
            float dnx = __shfl_sync(FULL, nbx, lane + 2);
            float dny = __shfl_sync(FULL, nby, lane + 2);
            float2 Tn = (g2 == 0) ? make_float2(ntx, nty) : make_float2(upx, upy);
            float2 Bn = (g2 == 7) ? make_float2(ntx, nty) : make_float2(dnx, dny);
            T[r] = Tn; B[r] = Bn;

            gx += Tn.x * Bn.x + Tn.y * Bn.y;     // Gram for next round,
            gy += Tn.x * Bn.y - Tn.y * Bn.x;     // overlapped with shuffles
        }
        float selN = (g2 == 0) ? d2 : a2;
        float upN  = __shfl_sync(FULL, selN, lane - 2);
        float dnN  = __shfl_sync(FULL, d2, lane + 2);
        nrmT = (g2 == 0) ? a2 : upN;
        nrmB = (g2 == 7) ? a2 : dnN;

        bx = gx + __shfl_xor_sync(FULL, gx, 1);
        by = gy + __shfl_xor_sync(FULL, gy, 1);
    }

    // ---- peeled final round: rotation only, no permutation, no norm track ----
    {
        float df   = nrmB - nrmT;
        float ab2  = fmaxf(bx * bx + by * by, 1e-30f);
        float rho2 = fmaf(df, df, 4.f * ab2);
        float rrho = rsqrtf(rho2);
        float rho  = rho2 * rrho;
        float adf  = fabsf(df);
        float rpa  = rho + adf;
        float rca  = frcp(rpa);
        float sgn  = (df >= 0.f) ? 1.f : -1.f;
        float hrr  = 0.5f * rrho;
        float c    = fsqrt_ap(rpa * hrr);
        float inv  = sgn * fsqrt_ap(4.f * hrr * rca);
        float wx = bx * inv, wy = by * inv;

        #pragma unroll
        for (int r = 0; r < 8; r++) {
            float tx = T[r].x, ty = T[r].y;
            float bxr = B[r].x, byr = B[r].y;
            T[r] = make_float2(c * tx - (wx * bxr + wy * byr),
                               c * ty - (wx * byr - wy * bxr));
            B[r] = make_float2((wx * tx - wy * ty) + c * bxr,
                               (wx * ty + wy * tx) + c * byr);
        }
    }

    // ---- exact norms, min selection (within each 16-lane half) ----
    {
        float nT = 0.f, nB = 0.f;
        #pragma unroll
        for (int r = 0; r < 8; r++) {
            nT += T[r].x * T[r].x + T[r].y * T[r].y;
            nB += B[r].x * B[r].x + B[r].y * B[r].y;
        }
        nT += __shfl_xor_sync(FULL, nT, 1);
        nB += __shfl_xor_sync(FULL, nB, 1);

        float v; int tg;
        if (nB < nT) { v = nB; tg = 2 * g2 + 1; } else { v = nT; tg = 2 * g2; }
        #pragma unroll
        for (int o = 2; o <= 8; o <<= 1) {
            float ov = __shfl_xor_sync(FULL, v, o);
            int   ot = __shfl_xor_sync(FULL, tg, o);
            if (ov < v || (ov == v && ot < tg)) { v = ov; tg = ot; }
        }

        float sc = rsqrtf(v);
        if (g2 == (tg >> 1)) {
            #pragma unroll
            for (int r = 0; r < 8; r++) {
                float2 cv = (tg & 1) ? B[r] : T[r];
                spsi[w][m][2 * r + rl2] = make_float2(cv.x * sc, cv.y * sc);
            }
        }
    }
    __syncwarp();

    // ---- loss epilogue (full warp per matrix) ----
    float contrib = 0.f;
    #pragma unroll
    for (int mm = 0; mm < 2; mm++) {
        float2 psi = (lane < 16) ? spsi[w][mm][lane] : make_float2(0.f, 0.f);
        float2 tsum = psi;
        #pragma unroll
        for (int o = 16; o > 0; o >>= 1) {
            tsum.x += __shfl_xor_sync(FULL, tsum.x, o);
            tsum.y += __shfl_xor_sync(FULL, tsum.y, o);
        }

        float2 u  = make_float2(0.f, 0.f);
        float2 v2 = make_float2(0.f, 0.f);
        #pragma unroll
        for (int j2 = 0; j2 < 16; j2++) {
            float2 pj = spsi[w][mm][j2];
            float2 rr = g_r[lane * 16 + j2];
            u.x += rr.x * pj.x - rr.y * pj.y;
            u.y += rr.x * pj.y + rr.y * pj.x;
            float2 r2 = g_r2[lane * 16 + j2];
            v2.x += r2.x * pj.x - r2.y * pj.y;
            v2.y += r2.x * pj.y + r2.y * pj.x;
        }
        float pos = u.x  * tsum.x + u.y  * tsum.y;   // Re(u * conj(t))
        float e2  = v2.x * tsum.x + v2.y * tsum.y;
        float dlt = pos - x2[mm];
        contrib += dlt * dlt + LAM * (e2 - pos * pos);
    }

    #pragma unroll
    for (int o = 16; o > 0; o >>= 1)
        contrib += __shfl_xor_sync(FULL, contrib, o);

    if (lane == 0) {
        atomicAdd(&g_Z.acc, (double)contrib);
        __threadfence();
        unsigned int t = atomicAdd(&g_Z.cnt, 1u);
        if (t == (unsigned)(NTOT / 2 - 1)) {
            double total = atomicAdd(&g_Z.acc, 0.0);   // coherent final read
            out[0] = (float)(total * (1.0 / (double)NTOT));
        }
    }
}

extern "C" void kernel_launch(void* const* d_in, const int* in_sizes, int n_in,
                              void* d_out, int out_size) {
    const float* Ar = (const float*)d_in[0];
    const float* Ai = (const float*)d_in[1];
    const float* X  = (const float*)d_in[2];
    float* out = (float*)d_out;

    void* zptr = nullptr;
    cudaGetSymbolAddress(&zptr, g_Z);
    cudaMemsetAsync(zptr, 0, sizeof(ZeroBlock), 0);

    precompute_kernel<<<DD, 256>>>(Ar, Ai);
    solve_kernel<<<NTOT / (WPB * 2), WPB * 32>>>(X, out);
}

// round 16
// speedup vs baseline: 1.6132x; 1.6132x over previous
#include <cuda_runtime.h>
#include <math.h>

#define DD     32
#define DIMN   16
#define NTOT   4096
#define EPSV   1e-5f
#define LAM    0.1f
#define NSWEEP 4
#define WPB    2       // warps per block; each warp solves 2 matrices (lane halves)

// ---------------- scratch (device globals: no allocation allowed) -----------
struct ZeroBlock {
    float2 G[DIMN * DIMN];   // sum_d A_d A_d^H (atomic accumulate)
    double acc;              // loss accumulator
    unsigned int cnt;        // completion ticket
};
__device__ ZeroBlock g_Z;
__device__ float2 g_S[DD * DIMN * DIMN];       // A_d + A_d^H
__device__ float2 g_r[DD * DIMN];              // column sums of A_d
__device__ float2 g_r2[DD * DIMN];             // column sums of A_d @ A_d

__device__ __forceinline__ float frcp(float a) {
    float r; asm("rcp.approx.f32 %0,%1;" : "=f"(r) : "f"(a)); return r;
}
__device__ __forceinline__ float fsqrt_ap(float a) {
    float r; asm("sqrt.approx.f32 %0,%1;" : "=f"(r) : "f"(a)); return r;
}

// ---------------- kernel 0: constants from A (one block per d, atomic G) ----
__global__ void precompute_kernel(const float* __restrict__ Ar,
                                  const float* __restrict__ Ai) {
    __shared__ float2 sr[DIMN];
    const int d = blockIdx.x;
    const int t = threadIdx.x;          // 256 threads, one per (i,j)
    const int i = t >> 4, j = t & 15;
    const float* ar = Ar + d * 256;
    const float* ai = Ai + d * 256;

    float arij = ar[i * 16 + j], aiij = ai[i * 16 + j];
    float arji = ar[j * 16 + i], aiji = ai[j * 16 + i];
    g_S[d * 256 + t] = make_float2(arij + arji, aiij - aiji);

    float gx = 0.f, gy = 0.f;
    #pragma unroll
    for (int k = 0; k < 16; k++) {
        float axr = ar[i * 16 + k], axi = ai[i * 16 + k];
        float bxr = ar[j * 16 + k], bxi = ai[j * 16 + k];
        gx += axr * bxr + axi * bxi;
        gy += axi * bxr - axr * bxi;
    }
    atomicAdd(&g_Z.G[t].x, gx);
    atomicAdd(&g_Z.G[t].y, gy);

    if (t < 16) {
        float2 s = make_float2(0.f, 0.f);
        #pragma unroll
        for (int ii = 0; ii < 16; ii++) {
            s.x += ar[ii * 16 + t];
            s.y += ai[ii * 16 + t];
        }
        sr[t] = s;
        g_r[d * 16 + t] = s;
    }
    __syncthreads();
    if (t < 16) {
        float2 s = make_float2(0.f, 0.f);
        #pragma unroll
        for (int k = 0; k < 16; k++) {
            float2 rk = sr[k];
            float axr = ar[k * 16 + t], axi = ai[k * 16 + t];
            s.x += rk.x * axr - rk.y * axi;
            s.y += rk.x * axi + rk.y * axr;
        }
        g_r2[d * 16 + t] = s;
    }
}

// ---------------- kernel 1: split-warp Jacobi, 2 matrices per warp ----------
// Matrix (lane>>4) lives in that 16-lane half: 8 column-pairs x 2 lanes,
// each lane holds rows {2r + (hl&1)} of columns {2*g2, 2*g2+1}.
__global__ void __launch_bounds__(WPB * 32)
solve_kernel(const float* __restrict__ X, float* __restrict__ out) {
    __shared__ float2 sH[WPB][DIMN * 17];        // build/transpose buffer
    __shared__ float2 spsi[WPB][2][DIMN];

    const int w     = threadIdx.x >> 5;
    const int lane  = threadIdx.x & 31;
    const int nbase = (blockIdx.x * WPB + w) * 2;
    const unsigned FULL = 0xffffffffu;

    const int m   = lane >> 4;       // which matrix of the pair
    const int hl  = lane & 15;       // lane within half
    const int g2  = hl >> 1;         // column-pair group 0..7
    const int rl2 = hl & 1;          // row parity within group

    float2* H = sH[w];
    float2 T[8], B[8];
    float  x2[2];
    float  nrmT, nrmB;

    // ---- build both H matrices (full warp per matrix, buffer reused) ----
    x2[0] = X[nbase * DD + lane];
    x2[1] = X[(nbase + 1) * DD + lane];

    #pragma unroll
    for (int mm = 0; mm < 2; mm++) {
        float sx2 = x2[mm] * x2[mm];
        #pragma unroll
        for (int o = 16; o > 0; o >>= 1) sx2 += __shfl_xor_sync(FULL, sx2, o);

        float2 acc[8];
        #pragma unroll
        for (int k = 0; k < 8; k++) {
            float2 gg = g_Z.G[k * 32 + lane];
            acc[k] = make_float2(0.5f * gg.x, 0.5f * gg.y);
        }
        #pragma unroll
        for (int d = 0; d < DD; d++) {
            float h = 0.5f * __shfl_sync(FULL, x2[mm], d);
            #pragma unroll
            for (int k = 0; k < 8; k++) {
                float2 s = g_S[d * 256 + k * 32 + lane];
                acc[k].x -= h * s.x;
                acc[k].y -= h * s.y;
            }
        }
        #pragma unroll
        for (int k = 0; k < 8; k++) {
            int e = k * 32 + lane;
            int i = e >> 4, j = e & 15;
            if (i == j) acc[k].x += EPSV + 0.5f * sx2;
            H[i * 17 + j] = acc[k];
        }
        __syncwarp();
        if (m == mm) {
            #pragma unroll
            for (int r = 0; r < 8; r++) {
                T[r] = H[(2 * r + rl2) * 17 + 2 * g2];
                B[r] = H[(2 * r + rl2) * 17 + 2 * g2 + 1];
            }
        }
        __syncwarp();
    }

    // exact initial column norms (pair = 2 lanes, butterfly xor 1)
    {
        float a = 0.f, d0 = 0.f;
        #pragma unroll
        for (int r = 0; r < 8; r++) {
            a  += T[r].x * T[r].x + T[r].y * T[r].y;
            d0 += B[r].x * B[r].x + B[r].y * B[r].y;
        }
        a  += __shfl_xor_sync(FULL, a,  1);
        d0 += __shfl_xor_sync(FULL, d0, 1);
        nrmT = a; nrmB = d0;
    }

    // ---- one-sided Jacobi, round-robin, tracked norms ----
    // Closed-form rotation: rho = sqrt(df^2+4|b|^2); c^2=(rho+|df|)/(2rho);
    // (s/|b|)^2 = 2/(rho(rho+|df|)); delta = 2|b|^2/(rho+|df|)
    // Guard is branchless: ab2 clamped to 1e-30 (never binds at data scale).
    const int NROUND = NSWEEP * 15;
    for (int it = 0; it < NROUND - 1; it++) {
        // Gram off-diagonal conj(T).B over the 8 rows this lane holds
        float bx = 0.f, by = 0.f;
        #pragma unroll
        for (int r = 0; r < 8; r++) {
            bx += T[r].x * B[r].x + T[r].y * B[r].y;
            by += T[r].x * B[r].y - T[r].y * B[r].x;
        }
        bx += __shfl_xor_sync(FULL, bx, 1);
        by += __shfl_xor_sync(FULL, by, 1);

        // rotation params (one SIMD chain serves both matrices)
        float df   = nrmB - nrmT;
        float ab2  = fmaxf(bx * bx + by * by, 1e-30f);
        float rho2 = fmaf(df, df, 4.f * ab2);
        float rrho = rsqrtf(rho2);
        float rho  = rho2 * rrho;
        float adf  = fabsf(df);
        float rpa  = rho + adf;
        float rca  = frcp(rpa);
        float sgn  = (df >= 0.f) ? 1.f : -1.f;
        float hrr  = 0.5f * rrho;
        float c    = fsqrt_ap(rpa * hrr);
        float inv  = sgn * fsqrt_ap(4.f * hrr * rca);   // s/|b|
        float delta = sgn * (2.f * ab2) * rca;
        float wx = bx * inv, wy = by * inv;
        float a2 = nrmT - delta;
        float d2 = nrmB + delta;

        // column update + fused round-robin permutation (within lane halves)
        #pragma unroll
        for (int r = 0; r < 8; r++) {
            float tx = T[r].x, ty = T[r].y;
            float bxr = B[r].x, byr = B[r].y;
            float ntx = c * tx - (wx * bxr + wy * byr);
            float nty = c * ty - (wx * byr - wy * bxr);
            float nbx = (wx * tx - wy * ty) + c * bxr;
            float nby = (wx * ty + wy * tx) + c * byr;

            float selx = (g2 == 0) ? nbx : ntx;
            float sely = (g2 == 0) ? nby : nty;
            float upx = __shfl_sync(FULL, selx, lane - 2);
            float upy = __shfl_sync(FULL, sely, lane - 2);
            float dnx = __shfl_sync(FULL, nbx, lane + 2);
            float dny = __shfl_sync(FULL, nby, lane + 2);
            T[r] = (g2 == 0) ? make_float2(ntx, nty) : make_float2(upx, upy);
            B[r] = (g2 == 7) ? make_float2(ntx, nty) : make_float2(dnx, dny);
        }
        float selN = (g2 == 0) ? d2 : a2;
        float upN  = __shfl_sync(FULL, selN, lane - 2);
        float dnN  = __shfl_sync(FULL, d2, lane + 2);
        nrmT = (g2 == 0) ? a2 : upN;
        nrmB = (g2 == 7) ? a2 : dnN;
    }

    // ---- peeled final round: rotation only, no permutation, no norm track ----
    {
        float bx = 0.f, by = 0.f;
        #pragma unroll
        for (int r = 0; r < 8; r++) {
            bx += T[r].x * B[r].x + T[r].y * B[r].y;
            by += T[r].x * B[r].y - T[r].y * B[r].x;
        }
        bx += __shfl_xor_sync(FULL, bx, 1);
        by += __shfl_xor_sync(FULL, by, 1);

        float df   = nrmB - nrmT;
        float ab2  = fmaxf(bx * bx + by * by, 1e-30f);
        float rho2 = fmaf(df, df, 4.f * ab2);
        float rrho = rsqrtf(rho2);
        float rho  = rho2 * rrho;
        float adf  = fabsf(df);
        float rpa  = rho + adf;
        float rca  = frcp(rpa);
        float sgn  = (df >= 0.f) ? 1.f : -1.f;
        float hrr  = 0.5f * rrho;
        float c    = fsqrt_ap(rpa * hrr);
        float inv  = sgn * fsqrt_ap(4.f * hrr * rca);
        float wx = bx * inv, wy = by * inv;

        #pragma unroll
        for (int r = 0; r < 8; r++) {
            float tx = T[r].x, ty = T[r].y;
            float bxr = B[r].x, byr = B[r].y;
            T[r] = make_float2(c * tx - (wx * bxr + wy * byr),
                               c * ty - (wx * byr - wy * bxr));
            B[r] = make_float2((wx * tx - wy * ty) + c * bxr,
                               (wx * ty + wy * tx) + c * byr);
        }
    }

    // ---- exact norms, min selection (within each 16-lane half) ----
    {
        float nT = 0.f, nB = 0.f;
        #pragma unroll
        for (int r = 0; r < 8; r++) {
            nT += T[r].x * T[r].x + T[r].y * T[r].y;
            nB += B[r].x * B[r].x + B[r].y * B[r].y;
        }
        nT += __shfl_xor_sync(FULL, nT, 1);
        nB += __shfl_xor_sync(FULL, nB, 1);

        float v; int tg;
        if (nB < nT) { v = nB; tg = 2 * g2 + 1; } else { v = nT; tg = 2 * g2; }
        #pragma unroll
        for (int o = 2; o <= 8; o <<= 1) {
            float ov = __shfl_xor_sync(FULL, v, o);
            int   ot = __shfl_xor_sync(FULL, tg, o);
            if (ov < v || (ov == v && ot < tg)) { v = ov; tg = ot; }
        }

        float sc = rsqrtf(v);
        if (g2 == (tg >> 1)) {
            #pragma unroll
            for (int r = 0; r < 8; r++) {
                float2 cv = (tg & 1) ? B[r] : T[r];
                spsi[w][m][2 * r + rl2] = make_float2(cv.x * sc, cv.y * sc);
            }
        }
    }
    __syncwarp();

    // ---- loss epilogue (full warp per matrix) ----
    float contrib = 0.f;
    #pragma unroll
    for (int mm = 0; mm < 2; mm++) {
        float2 psi = (lane < 16) ? spsi[w][mm][lane] : make_float2(0.f, 0.f);
        float2 tsum = psi;
        #pragma unroll
        for (int o = 16; o > 0; o >>= 1) {
            tsum.x += __shfl_xor_sync(FULL, tsum.x, o);
            tsum.y += __shfl_xor_sync(FULL, tsum.y, o);
        }

        float2 u  = make_float2(0.f, 0.f);
        float2 v2 = make_float2(0.f, 0.f);
        #pragma unroll
        for (int j2 = 0; j2 < 16; j2++) {
            float2 pj = spsi[w][mm][j2];
            float2 rr = g_r[lane * 16 + j2];
            u.x += rr.x * pj.x - rr.y * pj.y;
            u.y += rr.x * pj.y + rr.y * pj.x;
            float2 r2 = g_r2[lane * 16 + j2];
            v2.x += r2.x * pj.x - r2.y * pj.y;
            v2.y += r2.x * pj.y + r2.y * pj.x;
        }
        float pos = u.x  * tsum.x + u.y  * tsum.y;   // Re(u * conj(t))
        float e2  = v2.x * tsum.x + v2.y * tsum.y;
        float dlt = pos - x2[mm];
        contrib += dlt * dlt + LAM * (e2 - pos * pos);
    }

    #pragma unroll
    for (int o = 16; o > 0; o >>= 1)
        contrib += __shfl_xor_sync(FULL, contrib, o);

    if (lane == 0) {
        atomicAdd(&g_Z.acc, (double)contrib);
        __threadfence();
        unsigned int t = atomicAdd(&g_Z.cnt, 1u);
        if (t == (unsigned)(NTOT / 2 - 1)) {
            double total = atomicAdd(&g_Z.acc, 0.0);   // coherent final read
            out[0] = (float)(total * (1.0 / (double)NTOT));
        }
    }
}

extern "C" void kernel_launch(void* const* d_in, const int* in_sizes, int n_in,
                              void* d_out, int out_size) {
    const float* Ar = (const float*)d_in[0];
    const float* Ai = (const float*)d_in[1];
    const float* X  = (const float*)d_in[2];
    float* out = (float*)d_out;

    void* zptr = nullptr;
    cudaGetSymbolAddress(&zptr, g_Z);
    cudaMemsetAsync(zptr, 0, sizeof(ZeroBlock), 0);

    precompute_kernel<<<DD, 256>>>(Ar, Ai);
    solve_kernel<<<NTOT / (WPB * 2), WPB * 32>>>(X, out);
}

// round 17
// speedup vs baseline: 1.7782x; 1.1023x over previous
#include <cuda_runtime.h>
#include <math.h>

#define DD     32
#define DIMN   16
#define NTOT   4096
#define EPSV   1e-5f
#define LAM    0.1f
#define NSWEEP 4
#define WPB    2       // warps per block; each warp solves 2 matrices (lane halves)

// ---------------- scratch (device globals: no allocation allowed) -----------
struct alignas(16) ZeroBlock {
    float4 G4[DIMN * DIMN / 2];   // sum_d A_d A_d^H, 2 complex per float4
    double acc;                   // loss accumulator
    unsigned int cnt;             // completion ticket
};
__device__ ZeroBlock g_Z;
__device__ float4 g_S4[DD * DIMN * DIMN / 2];  // A_d + A_d^H, 2 complex per float4
__device__ float4 g_r4[DD * DIMN / 2];         // column sums of A_d
__device__ float4 g_r24[DD * DIMN / 2];        // column sums of A_d @ A_d

__device__ __forceinline__ float fsqrt_ap(float a) {
    float r; asm("sqrt.approx.f32 %0,%1;" : "=f"(r) : "f"(a)); return r;
}

// ---------------- kernel 0: constants from A (one block per d, atomic G) ----
__global__ void precompute_kernel(const float* __restrict__ Ar,
                                  const float* __restrict__ Ai) {
    __shared__ float2 sr[DIMN];
    const int d = blockIdx.x;
    const int t = threadIdx.x;          // 256 threads, one per (i,j)
    const int i = t >> 4, j = t & 15;
    const float* ar = Ar + d * 256;
    const float* ai = Ai + d * 256;

    float2* S2 = reinterpret_cast<float2*>(g_S4);
    float*  Gf = reinterpret_cast<float*>(g_Z.G4);

    float arij = ar[i * 16 + j], aiij = ai[i * 16 + j];
    float arji = ar[j * 16 + i], aiji = ai[j * 16 + i];
    S2[d * 256 + t] = make_float2(arij + arji, aiij - aiji);

    float gx = 0.f, gy = 0.f;
    #pragma unroll
    for (int k = 0; k < 16; k++) {
        float axr = ar[i * 16 + k], axi = ai[i * 16 + k];
        float bxr = ar[j * 16 + k], bxi = ai[j * 16 + k];
        gx += axr * bxr + axi * bxi;
        gy += axi * bxr - axr * bxi;
    }
    atomicAdd(&Gf[2 * t], gx);
    atomicAdd(&Gf[2 * t + 1], gy);

    float2* r2v  = reinterpret_cast<float2*>(g_r4);
    float2* r22v = reinterpret_cast<float2*>(g_r24);

    if (t < 16) {
        float2 s = make_float2(0.f, 0.f);
        #pragma unroll
        for (int ii = 0; ii < 16; ii++) {
            s.x += ar[ii * 16 + t];
            s.y += ai[ii * 16 + t];
        }
        sr[t] = s;
        r2v[d * 16 + t] = s;
    }
    __syncthreads();
    if (t < 16) {
        float2 s = make_float2(0.f, 0.f);
        #pragma unroll
        for (int k = 0; k < 16; k++) {
            float2 rk = sr[k];
            float axr = ar[k * 16 + t], axi = ai[k * 16 + t];
            s.x += rk.x * axr - rk.y * axi;
            s.y += rk.x * axi + rk.y * axr;
        }
        r22v[d * 16 + t] = s;
    }
}

// ---------------- kernel 1: split-warp Jacobi, 2 matrices per warp ----------
// Matrix (lane>>4) lives in that 16-lane half: 8 column-pairs x 2 lanes,
// each lane holds rows {2r + (hl&1)} of columns {2*g2, 2*g2+1}.
__global__ void __launch_bounds__(WPB * 32)
solve_kernel(const float* __restrict__ X, float* __restrict__ out) {
    __shared__ float2 sH[WPB][DIMN * 17];        // build/transpose buffer
    __shared__ float2 spsi[WPB][2][DIMN];

    const int w     = threadIdx.x >> 5;
    const int lane  = threadIdx.x & 31;
    const int nbase = (blockIdx.x * WPB + w) * 2;
    const unsigned FULL = 0xffffffffu;

    const int m   = lane >> 4;       // which matrix of the pair
    const int hl  = lane & 15;       // lane within half
    const int g2  = hl >> 1;         // column-pair group 0..7
    const int rl2 = hl & 1;          // row parity within group

    float2* H = sH[w];
    float2 T[8], B[8];
    float  x2[2];
    float  nrmT, nrmB;

    // ---- build both H matrices (full warp per matrix, buffer reused) ----
    // float4 loads: lane owns complex elements e0 = 2*(k4*32+lane), e0+1.
    x2[0] = X[nbase * DD + lane];
    x2[1] = X[(nbase + 1) * DD + lane];

    #pragma unroll
    for (int mm = 0; mm < 2; mm++) {
        float sx2 = x2[mm] * x2[mm];
        #pragma unroll
        for (int o = 16; o > 0; o >>= 1) sx2 += __shfl_xor_sync(FULL, sx2, o);

        float4 acc[4];
        #pragma unroll
        for (int k = 0; k < 4; k++) {
            float4 gg = g_Z.G4[k * 32 + lane];
            acc[k] = make_float4(0.5f * gg.x, 0.5f * gg.y,
                                 0.5f * gg.z, 0.5f * gg.w);
        }
        #pragma unroll
        for (int d = 0; d < DD; d++) {
            float h = 0.5f * __shfl_sync(FULL, x2[mm], d);
            #pragma unroll
            for (int k = 0; k < 4; k++) {
                float4 s = g_S4[d * 128 + k * 32 + lane];
                acc[k].x -= h * s.x;  acc[k].y -= h * s.y;
                acc[k].z -= h * s.z;  acc[k].w -= h * s.w;
            }
        }
        #pragma unroll
        for (int k = 0; k < 4; k++) {
            int e0 = (k * 32 + lane) * 2;        // even element
            int i0 = e0 >> 4, j0 = e0 & 15;      // e0+1 is same row, col j0+1
            float dadd = EPSV + 0.5f * sx2;
            if (i0 == j0)     acc[k].x += dadd;
            if (i0 == j0 + 1) acc[k].z += dadd;
            H[i0 * 17 + j0]     = make_float2(acc[k].x, acc[k].y);
            H[i0 * 17 + j0 + 1] = make_float2(acc[k].z, acc[k].w);
        }
        __syncwarp();
        if (m == mm) {
            #pragma unroll
            for (int r = 0; r < 8; r++) {
                T[r] = H[(2 * r + rl2) * 17 + 2 * g2];
                B[r] = H[(2 * r + rl2) * 17 + 2 * g2 + 1];
            }
        }
        __syncwarp();
    }

    // exact initial column norms (pair = 2 lanes, butterfly xor 1)
    {
        float a = 0.f, d0 = 0.f;
        #pragma unroll
        for (int r = 0; r < 8; r++) {
            a  += T[r].x * T[r].x + T[r].y * T[r].y;
            d0 += B[r].x * B[r].x + B[r].y * B[r].y;
        }
        a  += __shfl_xor_sync(FULL, a,  1);
        d0 += __shfl_xor_sync(FULL, d0, 1);
        nrmT = a; nrmB = d0;
    }

    // ---- one-sided Jacobi, round-robin, tracked norms ----
    // 3-MUFU rotation: rho = sqrt(df^2+4|b|^2); p = (rho+|df|)/(2rho);
    // c = sqrt(p); s/|b| = rrho/c = rrho*rsqrt(p); delta = sgn*(rho-|df|)/2.
    const int NROUND = NSWEEP * 15;
    for (int it = 0; it < NROUND - 1; it++) {
        // Gram off-diagonal conj(T).B over the 8 rows this lane holds
        float bx = 0.f, by = 0.f;
        #pragma unroll
        for (int r = 0; r < 8; r++) {
            bx += T[r].x * B[r].x + T[r].y * B[r].y;
            by += T[r].x * B[r].y - T[r].y * B[r].x;
        }
        bx += __shfl_xor_sync(FULL, bx, 1);
        by += __shfl_xor_sync(FULL, by, 1);

        // rotation params (one SIMD chain serves both matrices)
        float df   = nrmB - nrmT;
        float ab2  = fmaxf(bx * bx + by * by, 1e-30f);
        float rho2 = fmaf(df, df, 4.f * ab2);
        float rrho = rsqrtf(rho2);
        float rho  = rho2 * rrho;
        float adf  = fabsf(df);
        float sgn  = (df >= 0.f) ? 1.f : -1.f;
        float p    = (rho + adf) * (0.5f * rrho);
        float c    = fsqrt_ap(p);
        float inv  = sgn * rrho * rsqrtf(p);     // s/|b|
        float delta = sgn * 0.5f * (rho - adf);
        float wx = bx * inv, wy = by * inv;
        float a2 = nrmT - delta;
        float d2 = nrmB + delta;

        // column update + fused round-robin permutation (within lane halves)
        #pragma unroll
        for (int r = 0; r < 8; r++) {
            float tx = T[r].x, ty = T[r].y;
            float bxr = B[r].x, byr = B[r].y;
            float ntx = c * tx - (wx * bxr + wy * byr);
            float nty = c * ty - (wx * byr - wy * bxr);
            float nbx = (wx * tx - wy * ty) + c * bxr;
            float nby = (wx * ty + wy * tx) + c * byr;

            float selx = (g2 == 0) ? nbx : ntx;
            float sely = (g2 == 0) ? nby : nty;
            float upx = __shfl_sync(FULL, selx, lane - 2);
            float upy = __shfl_sync(FULL, sely, lane - 2);
            float dnx = __shfl_sync(FULL, nbx, lane + 2);
            float dny = __shfl_sync(FULL, nby, lane + 2);
            T[r] = (g2 == 0) ? make_float2(ntx, nty) : make_float2(upx, upy);
            B[r] = (g2 == 7) ? make_float2(ntx, nty) : make_float2(dnx, dny);
        }
        float selN = (g2 == 0) ? d2 : a2;
        float upN  = __shfl_sync(FULL, selN, lane - 2);
        float dnN  = __shfl_sync(FULL, d2, lane + 2);
        nrmT = (g2 == 0) ? a2 : upN;
        nrmB = (g2 == 7) ? a2 : dnN;
    }

    // ---- peeled final round: rotation only, no permutation, no norm track ----
    {
        float bx = 0.f, by = 0.f;
        #pragma unroll
        for (int r = 0; r < 8; r++) {
            bx += T[r].x * B[r].x + T[r].y * B[r].y;
            by += T[r].x * B[r].y - T[r].y * B[r].x;
        }
        bx += __shfl_xor_sync(FULL, bx, 1);
        by += __shfl_xor_sync(FULL, by, 1);

        float df   = nrmB - nrmT;
        float ab2  = fmaxf(bx * bx + by * by, 1e-30f);
        float rho2 = fmaf(df, df, 4.f * ab2);
        float rrho = rsqrtf(rho2);
        float rho  = rho2 * rrho;
        float adf  = fabsf(df);
        float sgn  = (df >= 0.f) ? 1.f : -1.f;
        float p    = (rho + adf) * (0.5f * rrho);
        float c    = fsqrt_ap(p);
        float inv  = sgn * rrho * rsqrtf(p);
        float wx = bx * inv, wy = by * inv;

        #pragma unroll
        for (int r = 0; r < 8; r++) {
            float tx = T[r].x, ty = T[r].y;
            float bxr = B[r].x, byr = B[r].y;
            T[r] = make_float2(c * tx - (wx * bxr + wy * byr),
                               c * ty - (wx * byr - wy * bxr));
            B[r] = make_float2((wx * tx - wy * ty) + c * bxr,
                               (wx * ty + wy * tx) + c * byr);
        }
    }

    // ---- exact norms, min selection (within each 16-lane half) ----
    {
        float nT = 0.f, nB = 0.f;
        #pragma unroll
        for (int r = 0; r < 8; r++) {
            nT += T[r].x * T[r].x + T[r].y * T[r].y;
            nB += B[r].x * B[r].x + B[r].y * B[r].y;
        }
        nT += __shfl_xor_sync(FULL, nT, 1);
        nB += __shfl_xor_sync(FULL, nB, 1);

        float v; int tg;
        if (nB < nT) { v = nB; tg = 2 * g2 + 1; } else { v = nT; tg = 2 * g2; }
        #pragma unroll
        for (int o = 2; o <= 8; o <<= 1) {
            float ov = __shfl_xor_sync(FULL, v, o);
            int   ot = __shfl_xor_sync(FULL, tg, o);
            if (ov < v || (ov == v && ot < tg)) { v = ov; tg = ot; }
        }

        float sc = rsqrtf(v);
        if (g2 == (tg >> 1)) {
            #pragma unroll
            for (int r = 0; r < 8; r++) {
                float2 cv = (tg & 1) ? B[r] : T[r];
                spsi[w][m][2 * r + rl2] = make_float2(cv.x * sc, cv.y * sc);
            }
        }
    }
    __syncwarp();

    // ---- loss epilogue (full warp per matrix, float4 constant loads) ----
    float contrib = 0.f;
    #pragma unroll
    for (int mm = 0; mm < 2; mm++) {
        float2 psi = (lane < 16) ? spsi[w][mm][lane] : make_float2(0.f, 0.f);
        float2 tsum = psi;
        #pragma unroll
        for (int o = 16; o > 0; o >>= 1) {
            tsum.x += __shfl_xor_sync(FULL, tsum.x, o);
            tsum.y += __shfl_xor_sync(FULL, tsum.y, o);
        }

        float2 u  = make_float2(0.f, 0.f);
        float2 v2 = make_float2(0.f, 0.f);
        #pragma unroll
        for (int jp = 0; jp < 8; jp++) {           // 2 complex per iteration
            float2 p0 = spsi[w][mm][2 * jp];
            float2 p1 = spsi[w][mm][2 * jp + 1];
            float4 rr = g_r4[lane * 8 + jp];
            float4 r2 = g_r24[lane * 8 + jp];
            u.x += rr.x * p0.x - rr.y * p0.y;  u.y += rr.x * p0.y + rr.y * p0.x;
            u.x += rr.z * p1.x - rr.w * p1.y;  u.y += rr.z * p1.y + rr.w * p1.x;
            v2.x += r2.x * p0.x - r2.y * p0.y; v2.y += r2.x * p0.y + r2.y * p0.x;
            v2.x += r2.z * p1.x - r2.w * p1.y; v2.y += r2.z * p1.y + r2.w * p1.x;
        }
        float pos = u.x  * tsum.x + u.y  * tsum.y;   // Re(u * conj(t))
        float e2  = v2.x * tsum.x + v2.y * tsum.y;
        float dlt = pos - x2[mm];
        contrib += dlt * dlt + LAM * (e2 - pos * pos);
    }

    #pragma unroll
    for (int o = 16; o > 0; o >>= 1)
        contrib += __shfl_xor_sync(FULL, contrib, o);

    if (lane == 0) {
        atomicAdd(&g_Z.acc, (double)contrib);
        __threadfence();
        unsigned int t = atomicAdd(&g_Z.cnt, 1u);
        if (t == (unsigned)(NTOT / 2 - 1)) {
            double total = atomicAdd(&g_Z.acc, 0.0);   // coherent final read
            out[0] = (float)(total * (1.0 / (double)NTOT));
        }
    }
}

extern "C" void kernel_launch(void* const* d_in, const int* in_sizes, int n_in,
                              void* d_out, int out_size) {
    const float* Ar = (const float*)d_in[0];
    const float* Ai = (const float*)d_in[1];
    const float* X  = (const float*)d_in[2];
    float* out = (float*)d_out;

    void* zptr = nullptr;
    cudaGetSymbolAddress(&zptr, g_Z);
    cudaMemsetAsync(zptr, 0, sizeof(ZeroBlock), 0);

    precompute_kernel<<<DD, 256>>>(Ar, Ai);
    solve_kernel<<<NTOT / (WPB * 2), WPB * 32>>>(X, out);
}